// round 5
// baseline (speedup 1.0000x reference)
#include <cuda_runtime.h>
#include <cuda_bf16.h>
#include <math.h>
#include <stdint.h>

#define D_MODEL 2048
#define NHEADS  16
#define DK      128
#define SEQ     2048
#define BATCH   2
#define MROWS   (BATCH*SEQ)
#define WSZ     (D_MODEL*D_MODEL)

// ---------------- scratch ----------------------------------------------------
__device__ __align__(256) float g_Q[BATCH*NHEADS*SEQ*DK];   // [b][h][s][dk]
__device__ __align__(256) float g_K[BATCH*NHEADS*SEQ*DK];
__device__ __align__(256) float g_V[BATCH*NHEADS*SEQ*DK];
__device__ __align__(256) __nv_bfloat16 g_xh[MROWS*D_MODEL];
__device__ __align__(256) __nv_bfloat16 g_xl[MROWS*D_MODEL];
__device__ __align__(256) __nv_bfloat16 g_wh[4*WSZ];
__device__ __align__(256) __nv_bfloat16 g_wl[4*WSZ];
__device__ __align__(256) __nv_bfloat16 g_ath[MROWS*D_MODEL];
__device__ __align__(256) __nv_bfloat16 g_atl[MROWS*D_MODEL];

// ========================= helpers ===========================================
__device__ __forceinline__ uint32_t smem_to_u32(const void* p) {
    uint32_t a;
    asm("{ .reg .u64 t; cvta.to.shared.u64 t, %1; cvt.u32.u64 %0, t; }"
        : "=r"(a) : "l"(p));
    return a;
}
__device__ __forceinline__ uint32_t swz(uint32_t off) {
    return off ^ (((off >> 7) & 7u) << 4);
}
#define CP_ASYNC16(dst, src) \
    asm volatile("cp.async.cg.shared.global [%0], [%1], 16;\n" :: "r"(dst), "l"(src))
#define CP_COMMIT() asm volatile("cp.async.commit_group;\n" ::: "memory")
#define CP_WAIT(n)  asm volatile("cp.async.wait_group %0;\n" :: "n"(n) : "memory")

#define LDMX4(r0, r1, r2, r3, addr) \
    asm volatile("ldmatrix.sync.aligned.m8n8.x4.shared.b16 {%0,%1,%2,%3}, [%4];" \
        : "=r"(r0), "=r"(r1), "=r"(r2), "=r"(r3) : "r"(addr))

#define MMA16816(d, a, b0, b1) \
    asm volatile("mma.sync.aligned.m16n8k16.row.col.f32.bf16.bf16.f32 " \
        "{%0,%1,%2,%3}, {%4,%5,%6,%7}, {%8,%9}, {%0,%1,%2,%3};" \
        : "+f"((d)[0]), "+f"((d)[1]), "+f"((d)[2]), "+f"((d)[3]) \
        : "r"((a)[0]), "r"((a)[1]), "r"((a)[2]), "r"((a)[3]), "r"(b0), "r"(b1))

// ========================= merged split conversion ===========================
__global__ void convert_all(const float* __restrict__ x,
                            const float* __restrict__ Wq,
                            const float* __restrict__ Wk,
                            const float* __restrict__ Wv,
                            const float* __restrict__ Wo)
{
    const int NX4 = MROWS * D_MODEL / 4;   // 2,097,152
    const int NW4 = WSZ / 4;               // 1,048,576 (2^20)
    int i4 = blockIdx.x * blockDim.x + threadIdx.x;
    const float* src;
    __nv_bfloat16 *hi, *lo;
    int off;
    if (i4 < NX4) {
        src = x; hi = g_xh; lo = g_xl; off = i4;
    } else {
        int j = i4 - NX4;
        int w = j >> 20;
        off   = j & (NW4 - 1);
        src = (w == 0) ? Wq : (w == 1) ? Wk : (w == 2) ? Wv : Wo;
        hi = g_wh + (size_t)w * WSZ;
        lo = g_wl + (size_t)w * WSZ;
    }
    float4 v = *(const float4*)(src + (size_t)off * 4);
    float f[4] = {v.x, v.y, v.z, v.w};
    __nv_bfloat16 h[4], l[4];
#pragma unroll
    for (int j = 0; j < 4; j++) {
        h[j] = __float2bfloat16(f[j]);
        l[j] = __float2bfloat16(f[j] - __bfloat162float(h[j]));
    }
    __nv_bfloat162* hp = (__nv_bfloat162*)(hi + (size_t)off * 4);
    __nv_bfloat162* lp = (__nv_bfloat162*)(lo + (size_t)off * 4);
    hp[0] = __nv_bfloat162(h[0], h[1]); hp[1] = __nv_bfloat162(h[2], h[3]);
    lp[0] = __nv_bfloat162(l[0], l[1]); lp[1] = __nv_bfloat162(l[2], l[3]);
}

// ========================= mma.sync GEMM =====================================
// C = A * B^T, hi/lo bf16 split (hh + lh + hl), fp32 acc.
// Tile 128x128, Kc=32, 3-stage cp.async ring (96KB) -> 2 CTAs/SM.
// mode 0: fused QKV (blockIdx.x picks weight+n-tile), scatter to g_Q/g_K/g_V.
// mode 3: A = attention output, B = Wo, write row-major to Cout.
#define KC      32
#define NK      (D_MODEL / KC)          // 64
#define MAT_B   8192                    // 128 rows x 64 bytes
#define STAGE_B (4 * MAT_B)             // Ah, Al, Bh, Bl
#define NSTAGE  3
#define GEMM_SMEM (NSTAGE * STAGE_B)    // 98304

__global__ __launch_bounds__(256, 2) void gemm_tc(float* __restrict__ Cout, int mode)
{
    extern __shared__ char smem[];
    const uint32_t sb = smem_to_u32(smem);
    const int t   = threadIdx.x;
    const int lid = t & 31;
    const int wid = t >> 5;
    const int m0  = blockIdx.y * 128;

    int w, n0;
    if (mode == 0) { w = blockIdx.x >> 4; n0 = (blockIdx.x & 15) * 128; }
    else           { w = 3;               n0 = blockIdx.x * 128; }

    const __nv_bfloat16* Ah = (mode == 0 ? g_xh : g_ath) + (size_t)m0 * D_MODEL;
    const __nv_bfloat16* Al = (mode == 0 ? g_xl : g_atl) + (size_t)m0 * D_MODEL;
    const __nv_bfloat16* Bh = g_wh + (size_t)w * WSZ + (size_t)n0 * D_MODEL;
    const __nv_bfloat16* Bl = g_wl + (size_t)w * WSZ + (size_t)n0 * D_MODEL;

    // loader role: 64 threads per matrix (Ah/Al/Bh/Bl), 8 x 16B chunks each
    const __nv_bfloat16* sp = (t < 64) ? Ah : (t < 128) ? Al : (t < 192) ? Bh : Bl;
    const int part = t >> 6;
    const int lt   = t & 63;

    auto load_chunk = [&](int buf, int k0) {
        uint32_t pbase = sb + buf * STAGE_B + part * MAT_B;
#pragma unroll
        for (int q = 0; q < 8; q++) {
            int cc  = lt + q * 64;          // 0..511
            int row = cc >> 2;              // 0..127
            int c   = cc & 3;
            uint32_t dst = pbase + swz((uint32_t)(row * 64 + c * 16));
            const __nv_bfloat16* src = sp + (size_t)row * D_MODEL + k0 + c * 8;
            CP_ASYNC16(dst, src);
        }
        CP_COMMIT();
    };

    // per-thread ldmatrix offsets: warp grid 4(m) x 2(n), 32x64 per warp
    const int wm  = wid & 3;
    const int wn  = wid >> 2;
    const int m0w = wm * 32;
    const int n0w = wn * 64;

    uint32_t aoff[2][2];
#pragma unroll
    for (int ks = 0; ks < 2; ks++)
#pragma unroll
        for (int mf = 0; mf < 2; mf++) {
            int row = m0w + mf * 16 + (lid & 15);
            int kb  = ((lid >> 4) * 8 + ks * 16) * 2;
            aoff[ks][mf] = swz((uint32_t)(row * 64 + kb));
        }
    uint32_t boff[2][4];
#pragma unroll
    for (int ks = 0; ks < 2; ks++)
#pragma unroll
        for (int nf = 0; nf < 4; nf++) {
            int row = n0w + nf * 16 + ((lid >> 4) << 3) + (lid & 7);
            int kb  = (((lid >> 3) & 1) * 8 + ks * 16) * 2;
            boff[ks][nf] = swz((uint32_t)(row * 64 + kb));
        }

    float acc[2][8][4];
#pragma unroll
    for (int i = 0; i < 2; i++)
#pragma unroll
        for (int j = 0; j < 8; j++)
#pragma unroll
            for (int q = 0; q < 4; q++) acc[i][j][q] = 0.f;

    load_chunk(0, 0);
    load_chunk(1, KC);

    int buf = 0;
    for (int k = 0; k < NK; k++) {
        if (k == NK - 1) CP_WAIT(0); else CP_WAIT(1);
        __syncthreads();
        if (k + 2 < NK) {
            int nb = buf + 2; if (nb >= NSTAGE) nb -= NSTAGE;
            load_chunk(nb, (k + 2) * KC);
        }

        uint32_t stg = sb + buf * STAGE_B;
#pragma unroll
        for (int ks = 0; ks < 2; ks++) {
            uint32_t a_h[2][4], a_l[2][4], bb[4][4];
#pragma unroll
            for (int mf = 0; mf < 2; mf++) {
                uint32_t ad = stg + aoff[ks][mf];
                LDMX4(a_h[mf][0], a_h[mf][1], a_h[mf][2], a_h[mf][3], ad);
                LDMX4(a_l[mf][0], a_l[mf][1], a_l[mf][2], a_l[mf][3], ad + MAT_B);
            }
#pragma unroll
            for (int nf = 0; nf < 4; nf++) {
                uint32_t bd = stg + 2 * MAT_B + boff[ks][nf];
                LDMX4(bb[nf][0], bb[nf][1], bb[nf][2], bb[nf][3], bd);
            }
            // pass 1: hh  (16 independent MMAs)
#pragma unroll
            for (int mf = 0; mf < 2; mf++)
#pragma unroll
                for (int nf = 0; nf < 4; nf++) {
                    MMA16816(acc[mf][2*nf],   a_h[mf], bb[nf][0], bb[nf][1]);
                    MMA16816(acc[mf][2*nf+1], a_h[mf], bb[nf][2], bb[nf][3]);
                }
            // pass 2: lh
#pragma unroll
            for (int mf = 0; mf < 2; mf++)
#pragma unroll
                for (int nf = 0; nf < 4; nf++) {
                    MMA16816(acc[mf][2*nf],   a_l[mf], bb[nf][0], bb[nf][1]);
                    MMA16816(acc[mf][2*nf+1], a_l[mf], bb[nf][2], bb[nf][3]);
                }
            // reload B as lo, pass 3: hl
#pragma unroll
            for (int nf = 0; nf < 4; nf++) {
                uint32_t bd = stg + 3 * MAT_B + boff[ks][nf];
                LDMX4(bb[nf][0], bb[nf][1], bb[nf][2], bb[nf][3], bd);
            }
#pragma unroll
            for (int mf = 0; mf < 2; mf++)
#pragma unroll
                for (int nf = 0; nf < 4; nf++) {
                    MMA16816(acc[mf][2*nf],   a_h[mf], bb[nf][0], bb[nf][1]);
                    MMA16816(acc[mf][2*nf+1], a_h[mf], bb[nf][2], bb[nf][3]);
                }
        }
        if (++buf >= NSTAGE) buf -= NSTAGE;
    }

    // epilogue
    const int rbase = m0 + m0w + (lid >> 2);
    const int cbase = n0w + (lid & 3) * 2;

#pragma unroll
    for (int mf = 0; mf < 2; mf++)
#pragma unroll
        for (int half = 0; half < 2; half++) {
            int m = rbase + mf * 16 + half * 8;
            float* dst;
            if (mode == 3) {
                dst = Cout + (size_t)m * D_MODEL + n0;
            } else {
                float* O = (w == 0) ? g_Q : (w == 1) ? g_K : g_V;
                int b = m >> 11;
                int s = m & (SEQ - 1);
                int h = n0 >> 7;
                dst = O + ((size_t)(b * NHEADS + h) * SEQ + s) * DK;
            }
#pragma unroll
            for (int n8 = 0; n8 < 8; n8++)
                *(float2*)(dst + cbase + n8 * 8) =
                    make_float2(acc[mf][n8][half * 2], acc[mf][n8][half * 2 + 1]);
        }
}

// ---------------- RoPE (in-place on g_Q and g_K) -----------------------------
__global__ void rope_kernel(const int* __restrict__ pos)
{
    const int NP = BATCH * NHEADS * SEQ * (DK / 2);
    int idx = blockIdx.x * blockDim.x + threadIdx.x;
    if (idx >= 2 * NP) return;
    float* T = (idx < NP) ? g_Q : g_K;
    int i  = (idx < NP) ? idx : idx - NP;
    int p  = i & 63;
    int s  = (i >> 6) & (SEQ - 1);
    int bh = i >> 17;
    int b  = bh >> 4;

    float position = (float)pos[b * SEQ + s];
    float inv = powf(10000.0f, -(float)(2 * p) * (1.0f / 128.0f));
    float ang = position * inv;
    float sn, cs;
    sincosf(ang, &sn, &cs);

    size_t base = ((size_t)bh * SEQ + s) * DK + 2 * p;
    float x1 = T[base], x2 = T[base + 1];
    T[base]     = x1 * cs - x2 * sn;
    T[base + 1] = x1 * sn + x2 * cs;
}

// ---------------- Flash attention (fp32, causal) -----------------------------
#define FQ   64
#define FKV  64
#define FPAD 132

__global__ __launch_bounds__(256) void flash_kernel()
{
    extern __shared__ float sh[];
    float* sQ = sh;
    float* sK = sQ + FQ * FPAD;
    float* sV = sK + FKV * FPAD;
    float* sP = sV + FKV * FPAD;

    const int t  = threadIdx.x;
    const int tx = t & 15;
    const int ty = t >> 4;
    const int bh = blockIdx.y;
    const int b  = bh >> 4;
    const int h  = bh & 15;
    const int q0 = blockIdx.x * FQ;

    const float* Qg = g_Q + ((size_t)(b * NHEADS + h) * SEQ) * DK;
    const float* Kg = g_K + ((size_t)(b * NHEADS + h) * SEQ) * DK;
    const float* Vg = g_V + ((size_t)(b * NHEADS + h) * SEQ) * DK;
    const float scale = 0.08838834764831843f;

#pragma unroll
    for (int i = 0; i < 8; i++) {
        int idx = t + i * 256;
        int row = idx >> 5;
        int c   = (idx & 31) << 2;
        float4 v = *(const float4*)(Qg + (size_t)(q0 + row) * DK + c);
        v.x *= scale; v.y *= scale; v.z *= scale; v.w *= scale;
        *(float4*)&sQ[row * FPAD + c] = v;
    }

    float m[4], l[4], o[4][8];
#pragma unroll
    for (int i = 0; i < 4; i++) {
        m[i] = -INFINITY; l[i] = 0.f;
#pragma unroll
        for (int j = 0; j < 8; j++) o[i][j] = 0.f;
    }

    for (int kv0 = 0; kv0 <= q0; kv0 += FKV) {
        __syncthreads();
#pragma unroll
        for (int i = 0; i < 8; i++) {
            int idx = t + i * 256;
            int row = idx >> 5;
            int c   = (idx & 31) << 2;
            *(float4*)&sK[row * FPAD + c] =
                *(const float4*)(Kg + (size_t)(kv0 + row) * DK + c);
            *(float4*)&sV[row * FPAD + c] =
                *(const float4*)(Vg + (size_t)(kv0 + row) * DK + c);
        }
        __syncthreads();

        float s[4][4];
#pragma unroll
        for (int i = 0; i < 4; i++)
#pragma unroll
            for (int j = 0; j < 4; j++) s[i][j] = 0.f;

#pragma unroll 8
        for (int d4 = 0; d4 < DK; d4 += 4) {
            float4 qv[4], kf[4];
#pragma unroll
            for (int i = 0; i < 4; i++)
                qv[i] = *(float4*)&sQ[(ty * 4 + i) * FPAD + d4];
#pragma unroll
            for (int j = 0; j < 4; j++)
                kf[j] = *(float4*)&sK[(tx * 4 + j) * FPAD + d4];
#pragma unroll
            for (int i = 0; i < 4; i++)
#pragma unroll
                for (int j = 0; j < 4; j++)
                    s[i][j] += qv[i].x * kf[j].x + qv[i].y * kf[j].y
                             + qv[i].z * kf[j].z + qv[i].w * kf[j].w;
        }

        if (kv0 == q0) {
#pragma unroll
            for (int i = 0; i < 4; i++)
#pragma unroll
                for (int j = 0; j < 4; j++)
                    if (tx * 4 + j > ty * 4 + i) s[i][j] = -INFINITY;
        }

#pragma unroll
        for (int i = 0; i < 4; i++) {
            float r = fmaxf(fmaxf(s[i][0], s[i][1]), fmaxf(s[i][2], s[i][3]));
#pragma unroll
            for (int off = 8; off > 0; off >>= 1)
                r = fmaxf(r, __shfl_xor_sync(0xffffffffu, r, off));
            float mn    = fmaxf(m[i], r);
            float alpha = __expf(m[i] - mn);
            m[i] = mn;
            float rs = 0.f;
#pragma unroll
            for (int j = 0; j < 4; j++) {
                float p = __expf(s[i][j] - mn);
                s[i][j] = p;
                rs += p;
            }
#pragma unroll
            for (int off = 8; off > 0; off >>= 1)
                rs += __shfl_xor_sync(0xffffffffu, rs, off);
            l[i] = l[i] * alpha + rs;
#pragma unroll
            for (int j = 0; j < 8; j++) o[i][j] *= alpha;
#pragma unroll
            for (int j = 0; j < 4; j++)
                sP[(ty * 4 + i) * FKV + tx * 4 + j] = s[i][j];
        }
        __syncthreads();

#pragma unroll 4
        for (int kk = 0; kk < FKV; kk++) {
            float4 v0 = *(float4*)&sV[kk * FPAD + tx * 8];
            float4 v1 = *(float4*)&sV[kk * FPAD + tx * 8 + 4];
#pragma unroll
            for (int i = 0; i < 4; i++) {
                float p = sP[(ty * 4 + i) * FKV + kk];
                o[i][0] += p * v0.x; o[i][1] += p * v0.y;
                o[i][2] += p * v0.z; o[i][3] += p * v0.w;
                o[i][4] += p * v1.x; o[i][5] += p * v1.y;
                o[i][6] += p * v1.z; o[i][7] += p * v1.w;
            }
        }
    }

#pragma unroll
    for (int i = 0; i < 4; i++) {
        float inv = 1.0f / l[i];
        int row = q0 + ty * 4 + i;
        size_t base = (size_t)(b * SEQ + row) * D_MODEL + h * DK + tx * 8;
        __nv_bfloat16 hv[8], lv[8];
#pragma unroll
        for (int j = 0; j < 8; j++) {
            float v = o[i][j] * inv;
            hv[j] = __float2bfloat16(v);
            lv[j] = __float2bfloat16(v - __bfloat162float(hv[j]));
        }
        __nv_bfloat162* hp = (__nv_bfloat162*)(g_ath + base);
        __nv_bfloat162* lp = (__nv_bfloat162*)(g_atl + base);
        hp[0] = __nv_bfloat162(hv[0], hv[1]); hp[1] = __nv_bfloat162(hv[2], hv[3]);
        hp[2] = __nv_bfloat162(hv[4], hv[5]); hp[3] = __nv_bfloat162(hv[6], hv[7]);
        lp[0] = __nv_bfloat162(lv[0], lv[1]); lp[1] = __nv_bfloat162(lv[2], lv[3]);
        lp[2] = __nv_bfloat162(lv[4], lv[5]); lp[3] = __nv_bfloat162(lv[6], lv[7]);
    }
}

// ---------------- launch ------------------------------------------------------
extern "C" void kernel_launch(void* const* d_in, const int* in_sizes, int n_in,
                              void* d_out, int out_size)
{
    const float* x   = (const float*)d_in[0];
    const int*   pos = (const int*)  d_in[1];
    const float* Wq  = (const float*)d_in[2];
    const float* Wk  = (const float*)d_in[3];
    const float* Wv  = (const float*)d_in[4];
    const float* Wo  = (const float*)d_in[5];
    float* out = (float*)d_out;

    int ncv = (MROWS * D_MODEL + 4 * WSZ) / 4;      // 6,291,456 float4s
    convert_all<<<ncv / 256, 256>>>(x, Wq, Wk, Wv, Wo);

    cudaFuncSetAttribute((const void*)gemm_tc,
                         cudaFuncAttributeMaxDynamicSharedMemorySize, GEMM_SMEM);
    gemm_tc<<<dim3(48, 32), 256, GEMM_SMEM>>>(nullptr, 0);   // fused QKV

    rope_kernel<<<(2 * BATCH * NHEADS * SEQ * (DK / 2)) / 256, 256>>>(pos);

    int fsmem = (3 * FQ * FPAD + FQ * FKV) * (int)sizeof(float);
    cudaFuncSetAttribute((const void*)flash_kernel,
                         cudaFuncAttributeMaxDynamicSharedMemorySize, fsmem);
    flash_kernel<<<dim3(SEQ / FQ, BATCH * NHEADS), 256, fsmem>>>();

    gemm_tc<<<dim3(16, 32), 256, GEMM_SMEM>>>(out, 3);       // output projection
}

// round 6
// speedup vs baseline: 1.0007x; 1.0007x over previous
#include <cuda_runtime.h>
#include <cuda_bf16.h>
#include <math.h>
#include <stdint.h>

#define D_MODEL 2048
#define NHEADS  16
#define DK      128
#define SEQ     2048
#define BATCH   2
#define MROWS   (BATCH*SEQ)
#define WSZ     (D_MODEL*D_MODEL)

// ---------------- scratch ----------------------------------------------------
__device__ __align__(256) float g_Q[BATCH*NHEADS*SEQ*DK];   // [b][h][s][dk]
__device__ __align__(256) float g_K[BATCH*NHEADS*SEQ*DK];
__device__ __align__(256) float g_V[BATCH*NHEADS*SEQ*DK];
__device__ __align__(256) __nv_bfloat16 g_xh[MROWS*D_MODEL];
__device__ __align__(256) __nv_bfloat16 g_xl[MROWS*D_MODEL];
__device__ __align__(256) __nv_bfloat16 g_wh[4*WSZ];
__device__ __align__(256) __nv_bfloat16 g_wl[4*WSZ];
__device__ __align__(256) __nv_bfloat16 g_ath[MROWS*D_MODEL];
__device__ __align__(256) __nv_bfloat16 g_atl[MROWS*D_MODEL];

// ========================= helpers ===========================================
__device__ __forceinline__ uint32_t smem_to_u32(const void* p) {
    uint32_t a;
    asm("{ .reg .u64 t; cvta.to.shared.u64 t, %1; cvt.u32.u64 %0, t; }"
        : "=r"(a) : "l"(p));
    return a;
}
__device__ __forceinline__ uint32_t swz(uint32_t off) {
    return off ^ (((off >> 7) & 7u) << 4);
}
#define CP_ASYNC16(dst, src) \
    asm volatile("cp.async.cg.shared.global [%0], [%1], 16;\n" :: "r"(dst), "l"(src))
#define CP_COMMIT() asm volatile("cp.async.commit_group;\n" ::: "memory")
#define CP_WAIT(n)  asm volatile("cp.async.wait_group %0;\n" :: "n"(n) : "memory")

#define LDMX4(r0, r1, r2, r3, addr) \
    asm volatile("ldmatrix.sync.aligned.m8n8.x4.shared.b16 {%0,%1,%2,%3}, [%4];" \
        : "=r"(r0), "=r"(r1), "=r"(r2), "=r"(r3) : "r"(addr))

#define MMA16816(d, a, b0, b1) \
    asm volatile("mma.sync.aligned.m16n8k16.row.col.f32.bf16.bf16.f32 " \
        "{%0,%1,%2,%3}, {%4,%5,%6,%7}, {%8,%9}, {%0,%1,%2,%3};" \
        : "+f"((d)[0]), "+f"((d)[1]), "+f"((d)[2]), "+f"((d)[3]) \
        : "r"((a)[0]), "r"((a)[1]), "r"((a)[2]), "r"((a)[3]), "r"(b0), "r"(b1))

// ========================= merged split conversion ===========================
__global__ void convert_all(const float* __restrict__ x,
                            const float* __restrict__ Wq,
                            const float* __restrict__ Wk,
                            const float* __restrict__ Wv,
                            const float* __restrict__ Wo)
{
    const int NX4 = MROWS * D_MODEL / 4;   // 2,097,152
    const int NW4 = WSZ / 4;               // 1,048,576 (2^20)
    int i4 = blockIdx.x * blockDim.x + threadIdx.x;
    const float* src;
    __nv_bfloat16 *hi, *lo;
    int off;
    if (i4 < NX4) {
        src = x; hi = g_xh; lo = g_xl; off = i4;
    } else {
        int j = i4 - NX4;
        int w = j >> 20;
        off   = j & (NW4 - 1);
        src = (w == 0) ? Wq : (w == 1) ? Wk : (w == 2) ? Wv : Wo;
        hi = g_wh + (size_t)w * WSZ;
        lo = g_wl + (size_t)w * WSZ;
    }
    float4 v = *(const float4*)(src + (size_t)off * 4);
    float f[4] = {v.x, v.y, v.z, v.w};
    __nv_bfloat16 h[4], l[4];
#pragma unroll
    for (int j = 0; j < 4; j++) {
        h[j] = __float2bfloat16(f[j]);
        l[j] = __float2bfloat16(f[j] - __bfloat162float(h[j]));
    }
    __nv_bfloat162* hp = (__nv_bfloat162*)(hi + (size_t)off * 4);
    __nv_bfloat162* lp = (__nv_bfloat162*)(lo + (size_t)off * 4);
    hp[0] = __nv_bfloat162(h[0], h[1]); hp[1] = __nv_bfloat162(h[2], h[3]);
    lp[0] = __nv_bfloat162(l[0], l[1]); lp[1] = __nv_bfloat162(l[2], l[3]);
}

// ========================= mma.sync GEMM =====================================
// C = A * B^T, hi/lo bf16 split (hh + lh + hl), fp32 acc.
// Tile 128x128, Kc=32, 3-stage cp.async ring (96KB) -> 2 CTAs/SM.
// mode 0: fused QKV (blockIdx.x picks weight+n-tile), scatter to g_Q/g_K/g_V.
// mode 3: A = attention output, B = Wo, write row-major to Cout.
#define KC      32
#define NK      (D_MODEL / KC)          // 64
#define MAT_B   8192                    // 128 rows x 64 bytes
#define STAGE_B (4 * MAT_B)             // Ah, Al, Bh, Bl
#define NSTAGE  3
#define GEMM_SMEM (NSTAGE * STAGE_B)    // 98304

__global__ __launch_bounds__(256, 2) void gemm_tc(float* __restrict__ Cout, int mode)
{
    extern __shared__ char smem[];
    const uint32_t sb = smem_to_u32(smem);
    const int t   = threadIdx.x;
    const int lid = t & 31;
    const int wid = t >> 5;
    const int m0  = blockIdx.y * 128;

    int w, n0;
    if (mode == 0) { w = blockIdx.x >> 4; n0 = (blockIdx.x & 15) * 128; }
    else           { w = 3;               n0 = blockIdx.x * 128; }

    const __nv_bfloat16* Ah = (mode == 0 ? g_xh : g_ath) + (size_t)m0 * D_MODEL;
    const __nv_bfloat16* Al = (mode == 0 ? g_xl : g_atl) + (size_t)m0 * D_MODEL;
    const __nv_bfloat16* Bh = g_wh + (size_t)w * WSZ + (size_t)n0 * D_MODEL;
    const __nv_bfloat16* Bl = g_wl + (size_t)w * WSZ + (size_t)n0 * D_MODEL;

    // loader role: 64 threads per matrix (Ah/Al/Bh/Bl), 8 x 16B chunks each
    const __nv_bfloat16* sp = (t < 64) ? Ah : (t < 128) ? Al : (t < 192) ? Bh : Bl;
    const int part = t >> 6;
    const int lt   = t & 63;

    auto load_chunk = [&](int buf, int k0) {
        uint32_t pbase = sb + buf * STAGE_B + part * MAT_B;
#pragma unroll
        for (int q = 0; q < 8; q++) {
            int cc  = lt + q * 64;          // 0..511
            int row = cc >> 2;              // 0..127
            int c   = cc & 3;
            uint32_t dst = pbase + swz((uint32_t)(row * 64 + c * 16));
            const __nv_bfloat16* src = sp + (size_t)row * D_MODEL + k0 + c * 8;
            CP_ASYNC16(dst, src);
        }
        CP_COMMIT();
    };

    // per-thread ldmatrix offsets: warp grid 4(m) x 2(n), 32x64 per warp
    const int wm  = wid & 3;
    const int wn  = wid >> 2;
    const int m0w = wm * 32;
    const int n0w = wn * 64;

    uint32_t aoff[2][2];
#pragma unroll
    for (int ks = 0; ks < 2; ks++)
#pragma unroll
        for (int mf = 0; mf < 2; mf++) {
            int row = m0w + mf * 16 + (lid & 15);
            int kb  = ((lid >> 4) * 8 + ks * 16) * 2;
            aoff[ks][mf] = swz((uint32_t)(row * 64 + kb));
        }
    uint32_t boff[2][4];
#pragma unroll
    for (int ks = 0; ks < 2; ks++)
#pragma unroll
        for (int nf = 0; nf < 4; nf++) {
            int row = n0w + nf * 16 + ((lid >> 4) << 3) + (lid & 7);
            int kb  = (((lid >> 3) & 1) * 8 + ks * 16) * 2;
            boff[ks][nf] = swz((uint32_t)(row * 64 + kb));
        }

    float acc[2][8][4];
#pragma unroll
    for (int i = 0; i < 2; i++)
#pragma unroll
        for (int j = 0; j < 8; j++)
#pragma unroll
            for (int q = 0; q < 4; q++) acc[i][j][q] = 0.f;

    load_chunk(0, 0);
    load_chunk(1, KC);

    int buf = 0;
    for (int k = 0; k < NK; k++) {
        if (k == NK - 1) CP_WAIT(0); else CP_WAIT(1);
        __syncthreads();
        if (k + 2 < NK) {
            int nb = buf + 2; if (nb >= NSTAGE) nb -= NSTAGE;
            load_chunk(nb, (k + 2) * KC);
        }

        uint32_t stg = sb + buf * STAGE_B;
#pragma unroll
        for (int ks = 0; ks < 2; ks++) {
            uint32_t a_h[2][4], a_l[2][4], bb[4][4];
#pragma unroll
            for (int mf = 0; mf < 2; mf++) {
                uint32_t ad = stg + aoff[ks][mf];
                LDMX4(a_h[mf][0], a_h[mf][1], a_h[mf][2], a_h[mf][3], ad);
                LDMX4(a_l[mf][0], a_l[mf][1], a_l[mf][2], a_l[mf][3], ad + MAT_B);
            }
#pragma unroll
            for (int nf = 0; nf < 4; nf++) {
                uint32_t bd = stg + 2 * MAT_B + boff[ks][nf];
                LDMX4(bb[nf][0], bb[nf][1], bb[nf][2], bb[nf][3], bd);
            }
            // pass 1: hh  (16 independent MMAs)
#pragma unroll
            for (int mf = 0; mf < 2; mf++)
#pragma unroll
                for (int nf = 0; nf < 4; nf++) {
                    MMA16816(acc[mf][2*nf],   a_h[mf], bb[nf][0], bb[nf][1]);
                    MMA16816(acc[mf][2*nf+1], a_h[mf], bb[nf][2], bb[nf][3]);
                }
            // pass 2: lh
#pragma unroll
            for (int mf = 0; mf < 2; mf++)
#pragma unroll
                for (int nf = 0; nf < 4; nf++) {
                    MMA16816(acc[mf][2*nf],   a_l[mf], bb[nf][0], bb[nf][1]);
                    MMA16816(acc[mf][2*nf+1], a_l[mf], bb[nf][2], bb[nf][3]);
                }
            // reload B as lo, pass 3: hl
#pragma unroll
            for (int nf = 0; nf < 4; nf++) {
                uint32_t bd = stg + 3 * MAT_B + boff[ks][nf];
                LDMX4(bb[nf][0], bb[nf][1], bb[nf][2], bb[nf][3], bd);
            }
#pragma unroll
            for (int mf = 0; mf < 2; mf++)
#pragma unroll
                for (int nf = 0; nf < 4; nf++) {
                    MMA16816(acc[mf][2*nf],   a_h[mf], bb[nf][0], bb[nf][1]);
                    MMA16816(acc[mf][2*nf+1], a_h[mf], bb[nf][2], bb[nf][3]);
                }
        }
        if (++buf >= NSTAGE) buf -= NSTAGE;
    }

    // epilogue
    const int rbase = m0 + m0w + (lid >> 2);
    const int cbase = n0w + (lid & 3) * 2;

#pragma unroll
    for (int mf = 0; mf < 2; mf++)
#pragma unroll
        for (int half = 0; half < 2; half++) {
            int m = rbase + mf * 16 + half * 8;
            float* dst;
            if (mode == 3) {
                dst = Cout + (size_t)m * D_MODEL + n0;
            } else {
                float* O = (w == 0) ? g_Q : (w == 1) ? g_K : g_V;
                int b = m >> 11;
                int s = m & (SEQ - 1);
                int h = n0 >> 7;
                dst = O + ((size_t)(b * NHEADS + h) * SEQ + s) * DK;
            }
#pragma unroll
            for (int n8 = 0; n8 < 8; n8++)
                *(float2*)(dst + cbase + n8 * 8) =
                    make_float2(acc[mf][n8][half * 2], acc[mf][n8][half * 2 + 1]);
        }
}

// ---------------- RoPE (in-place on g_Q and g_K) -----------------------------
__global__ void rope_kernel(const int* __restrict__ pos)
{
    const int NP = BATCH * NHEADS * SEQ * (DK / 2);
    int idx = blockIdx.x * blockDim.x + threadIdx.x;
    if (idx >= 2 * NP) return;
    float* T = (idx < NP) ? g_Q : g_K;
    int i  = (idx < NP) ? idx : idx - NP;
    int p  = i & 63;
    int s  = (i >> 6) & (SEQ - 1);
    int bh = i >> 17;
    int b  = bh >> 4;

    float position = (float)pos[b * SEQ + s];
    float inv = powf(10000.0f, -(float)(2 * p) * (1.0f / 128.0f));
    float ang = position * inv;
    float sn, cs;
    sincosf(ang, &sn, &cs);

    size_t base = ((size_t)bh * SEQ + s) * DK + 2 * p;
    float x1 = T[base], x2 = T[base + 1];
    T[base]     = x1 * cs - x2 * sn;
    T[base + 1] = x1 * sn + x2 * cs;
}

// ---------------- Flash attention (fp32, causal) -----------------------------
#define FQ   64
#define FKV  64
#define FPAD 132

__global__ __launch_bounds__(256) void flash_kernel()
{
    extern __shared__ float sh[];
    float* sQ = sh;
    float* sK = sQ + FQ * FPAD;
    float* sV = sK + FKV * FPAD;
    float* sP = sV + FKV * FPAD;

    const int t  = threadIdx.x;
    const int tx = t & 15;
    const int ty = t >> 4;
    const int bh = blockIdx.y;
    const int b  = bh >> 4;
    const int h  = bh & 15;
    const int q0 = blockIdx.x * FQ;

    const float* Qg = g_Q + ((size_t)(b * NHEADS + h) * SEQ) * DK;
    const float* Kg = g_K + ((size_t)(b * NHEADS + h) * SEQ) * DK;
    const float* Vg = g_V + ((size_t)(b * NHEADS + h) * SEQ) * DK;
    const float scale = 0.08838834764831843f;

#pragma unroll
    for (int i = 0; i < 8; i++) {
        int idx = t + i * 256;
        int row = idx >> 5;
        int c   = (idx & 31) << 2;
        float4 v = *(const float4*)(Qg + (size_t)(q0 + row) * DK + c);
        v.x *= scale; v.y *= scale; v.z *= scale; v.w *= scale;
        *(float4*)&sQ[row * FPAD + c] = v;
    }

    float m[4], l[4], o[4][8];
#pragma unroll
    for (int i = 0; i < 4; i++) {
        m[i] = -INFINITY; l[i] = 0.f;
#pragma unroll
        for (int j = 0; j < 8; j++) o[i][j] = 0.f;
    }

    for (int kv0 = 0; kv0 <= q0; kv0 += FKV) {
        __syncthreads();
#pragma unroll
        for (int i = 0; i < 8; i++) {
            int idx = t + i * 256;
            int row = idx >> 5;
            int c   = (idx & 31) << 2;
            *(float4*)&sK[row * FPAD + c] =
                *(const float4*)(Kg + (size_t)(kv0 + row) * DK + c);
            *(float4*)&sV[row * FPAD + c] =
                *(const float4*)(Vg + (size_t)(kv0 + row) * DK + c);
        }
        __syncthreads();

        float s[4][4];
#pragma unroll
        for (int i = 0; i < 4; i++)
#pragma unroll
            for (int j = 0; j < 4; j++) s[i][j] = 0.f;

#pragma unroll 8
        for (int d4 = 0; d4 < DK; d4 += 4) {
            float4 qv[4], kf[4];
#pragma unroll
            for (int i = 0; i < 4; i++)
                qv[i] = *(float4*)&sQ[(ty * 4 + i) * FPAD + d4];
#pragma unroll
            for (int j = 0; j < 4; j++)
                kf[j] = *(float4*)&sK[(tx * 4 + j) * FPAD + d4];
#pragma unroll
            for (int i = 0; i < 4; i++)
#pragma unroll
                for (int j = 0; j < 4; j++)
                    s[i][j] += qv[i].x * kf[j].x + qv[i].y * kf[j].y
                             + qv[i].z * kf[j].z + qv[i].w * kf[j].w;
        }

        if (kv0 == q0) {
#pragma unroll
            for (int i = 0; i < 4; i++)
#pragma unroll
                for (int j = 0; j < 4; j++)
                    if (tx * 4 + j > ty * 4 + i) s[i][j] = -INFINITY;
        }

#pragma unroll
        for (int i = 0; i < 4; i++) {
            float r = fmaxf(fmaxf(s[i][0], s[i][1]), fmaxf(s[i][2], s[i][3]));
#pragma unroll
            for (int off = 8; off > 0; off >>= 1)
                r = fmaxf(r, __shfl_xor_sync(0xffffffffu, r, off));
            float mn    = fmaxf(m[i], r);
            float alpha = __expf(m[i] - mn);
            m[i] = mn;
            float rs = 0.f;
#pragma unroll
            for (int j = 0; j < 4; j++) {
                float p = __expf(s[i][j] - mn);
                s[i][j] = p;
                rs += p;
            }
#pragma unroll
            for (int off = 8; off > 0; off >>= 1)
                rs += __shfl_xor_sync(0xffffffffu, rs, off);
            l[i] = l[i] * alpha + rs;
#pragma unroll
            for (int j = 0; j < 8; j++) o[i][j] *= alpha;
#pragma unroll
            for (int j = 0; j < 4; j++)
                sP[(ty * 4 + i) * FKV + tx * 4 + j] = s[i][j];
        }
        __syncthreads();

#pragma unroll 4
        for (int kk = 0; kk < FKV; kk++) {
            float4 v0 = *(float4*)&sV[kk * FPAD + tx * 8];
            float4 v1 = *(float4*)&sV[kk * FPAD + tx * 8 + 4];
#pragma unroll
            for (int i = 0; i < 4; i++) {
                float p = sP[(ty * 4 + i) * FKV + kk];
                o[i][0] += p * v0.x; o[i][1] += p * v0.y;
                o[i][2] += p * v0.z; o[i][3] += p * v0.w;
                o[i][4] += p * v1.x; o[i][5] += p * v1.y;
                o[i][6] += p * v1.z; o[i][7] += p * v1.w;
            }
        }
    }

#pragma unroll
    for (int i = 0; i < 4; i++) {
        float inv = 1.0f / l[i];
        int row = q0 + ty * 4 + i;
        size_t base = (size_t)(b * SEQ + row) * D_MODEL + h * DK + tx * 8;
        __nv_bfloat16 hv[8], lv[8];
#pragma unroll
        for (int j = 0; j < 8; j++) {
            float v = o[i][j] * inv;
            hv[j] = __float2bfloat16(v);
            lv[j] = __float2bfloat16(v - __bfloat162float(hv[j]));
        }
        __nv_bfloat162* hp = (__nv_bfloat162*)(g_ath + base);
        __nv_bfloat162* lp = (__nv_bfloat162*)(g_atl + base);
        hp[0] = __nv_bfloat162(hv[0], hv[1]); hp[1] = __nv_bfloat162(hv[2], hv[3]);
        hp[2] = __nv_bfloat162(hv[4], hv[5]); hp[3] = __nv_bfloat162(hv[6], hv[7]);
        lp[0] = __nv_bfloat162(lv[0], lv[1]); lp[1] = __nv_bfloat162(lv[2], lv[3]);
        lp[2] = __nv_bfloat162(lv[4], lv[5]); lp[3] = __nv_bfloat162(lv[6], lv[7]);
    }
}

// ---------------- launch ------------------------------------------------------
extern "C" void kernel_launch(void* const* d_in, const int* in_sizes, int n_in,
                              void* d_out, int out_size)
{
    const float* x   = (const float*)d_in[0];
    const int*   pos = (const int*)  d_in[1];
    const float* Wq  = (const float*)d_in[2];
    const float* Wk  = (const float*)d_in[3];
    const float* Wv  = (const float*)d_in[4];
    const float* Wo  = (const float*)d_in[5];
    float* out = (float*)d_out;

    int ncv = (MROWS * D_MODEL + 4 * WSZ) / 4;      // 6,291,456 float4s
    convert_all<<<ncv / 256, 256>>>(x, Wq, Wk, Wv, Wo);

    cudaFuncSetAttribute((const void*)gemm_tc,
                         cudaFuncAttributeMaxDynamicSharedMemorySize, GEMM_SMEM);
    gemm_tc<<<dim3(48, 32), 256, GEMM_SMEM>>>(nullptr, 0);   // fused QKV

    rope_kernel<<<(2 * BATCH * NHEADS * SEQ * (DK / 2)) / 256, 256>>>(pos);

    int fsmem = (3 * FQ * FPAD + FQ * FKV) * (int)sizeof(float);
    cudaFuncSetAttribute((const void*)flash_kernel,
                         cudaFuncAttributeMaxDynamicSharedMemorySize, fsmem);
    flash_kernel<<<dim3(SEQ / FQ, BATCH * NHEADS), 256, fsmem>>>();

    gemm_tc<<<dim3(16, 32), 256, GEMM_SMEM>>>(out, 3);       // output projection
}